// round 9
// baseline (speedup 1.0000x reference)
#include <cuda_runtime.h>

// Net0: x[B,2] -> fc1(2,7)+ELU -> 19x fc(7,7)+ELU -> fc(7,2) -> log_softmax.
// R9: 4 rows/thread, FFMA2 matmuls, TWO structural changes:
//  (a) t-scale fold: accumulator is t = z*log2e, activation is G = log2e*g
//      where g = elu(z)+1. Since ln2*log2e = 1, MID-LAYER WEIGHTS ARE RAW;
//      only biases scale:  t_next = W*G + log2e*(b - rowsum(W)).
//      ELU: G = max(t,0) + log2e*min(exp2(t),1)  -> MUFU,MIN,MAX,FFMA-imm.
//  (b) j-major (transposed) matmul: h[j] is consumed once per j, so no hn[]
//      double-buffer -> ~64 regs -> __launch_bounds__(256,4) -> 8 warps/SMSP.

constexpr int H       = 7;
constexpr int NMID    = 19;
constexpr int THREADS = 256;
// per-layer shared layout (float2 units, 16B blocks):
//   jblk[j] (j=0..6): 8 float2 = {W[0][j]d .. W[6][j]d, pad}
//   biasblk:          8 float2 = {b'[0]d .. b'[6]d, pad}   (b' in t-scale)
// layer stride = 64 float2 = 512 B = 32 ulonglong2
constexpr int LSTRIDE_F2 = 64;
constexpr int LSTRIDE_U2 = 32;

typedef unsigned long long u64;

__device__ __forceinline__ u64 pack2(float lo, float hi) {
    u64 r; asm("mov.b64 %0, {%1, %2};" : "=l"(r) : "f"(lo), "f"(hi)); return r;
}
__device__ __forceinline__ void unpack2(u64 v, float& lo, float& hi) {
    asm("mov.b64 {%0, %1}, %2;" : "=f"(lo), "=f"(hi) : "l"(v));
}
__device__ __forceinline__ u64 fma2(u64 a, u64 b, u64 c) {
    u64 d; asm("fma.rn.f32x2 %0, %1, %2, %3;" : "=l"(d) : "l"(a), "l"(b), "l"(c));
    return d;
}
__device__ __forceinline__ float ex2f(float x) {
    float r; asm("ex2.approx.f32 %0, %1;" : "=f"(r) : "f"(x)); return r;
}

// Input t = z*log2e. Output G = log2e*(elu(z)+1) = max(t,0) + log2e*min(2^t,1).
// Per half: MUFU.EX2 + FMNMX(min) + FMNMX(max) + FFMA-imm (rt1).
__device__ __forceinline__ u64 eluG(u64 t) {
    u64 g;
    asm("{\n\t"
        ".reg .f32 tl, th, el, eh;\n\t"
        "mov.b64 {tl, th}, %1;\n\t"
        "ex2.approx.f32 el, tl;\n\t"
        "ex2.approx.f32 eh, th;\n\t"
        "min.f32 el, el, 0f3F800000;\n\t"
        "min.f32 eh, eh, 0f3F800000;\n\t"
        "max.f32 tl, tl, 0f00000000;\n\t"
        "max.f32 th, th, 0f00000000;\n\t"
        "fma.rn.f32 tl, el, 0f3FB8AA3B, tl;\n\t"   // log2e*min + max
        "fma.rn.f32 th, eh, 0f3FB8AA3B, th;\n\t"
        "mov.b64 %0, {tl, th};\n\t"
        "}" : "=l"(g) : "l"(t));
    return g;
}

__global__ void __launch_bounds__(THREADS, 4)
net0_kernel(const float* __restrict__ x,
            const float* __restrict__ W1, const float* __restrict__ b1,
            const float* __restrict__ Wm, const float* __restrict__ bm,
            const float* __restrict__ Wo, const float* __restrict__ bo,
            float* __restrict__ out, int nQuads)
{
    __shared__ __align__(16) float2 sFc1[H * 4];              // per i: {w0d,w1d,bd,pad} x log2e
    __shared__ __align__(16) float2 sMid[NMID * LSTRIDE_F2];  // j-major, raw W, bias' t-scale
    __shared__ __align__(16) float2 sFcO[2 * 8];              // per r: 7 (ln2*Wo)d + bias-fold d

    const float LOG2E = 1.44269504088896340736f;
    const float LN2   = 0.69314718055994530942f;

    // fc1: scaled by log2e (accumulator directly in t-scale).
    for (int idx = threadIdx.x; idx < H * 4; idx += THREADS) {
        int i = idx >> 2, k = idx & 3;
        float v = (k < 2) ? W1[i * 2 + k] * LOG2E
                          : (k == 2 ? b1[i] * LOG2E : 0.0f);
        sFc1[idx] = make_float2(v, v);
    }
    // mid layers, j-major: jblk[j][i] = Wm[l][i][j] (RAW), bias' = (b - rowsum)*log2e.
    for (int idx = threadIdx.x; idx < NMID * LSTRIDE_F2; idx += THREADS) {
        int l   = idx >> 6;           // / 64
        int r   = idx & 63;
        int blk = r >> 3;             // 0..7
        int k   = r & 7;              // 0..7
        float v = 0.0f;
        if (blk < 7) {                // weight block j=blk, neuron i=k
            if (k < 7) v = Wm[(l * H + k) * H + blk];
        } else {                      // bias block
            if (k < 7) {
                float s = 0.0f;
                for (int j = 0; j < H; j++) s += Wm[(l * H + k) * H + j];
                v = (bm[l * H + k] - s) * LOG2E;
            }
        }
        sMid[idx] = make_float2(v, v);
    }
    // fc21: consumes G: logits = (ln2*Wo)*G + (bo - rowsum(Wo)).
    for (int idx = threadIdx.x; idx < 16; idx += THREADS) {
        int r = idx >> 3, k = idx & 7;
        float v;
        if (k < 7) {
            v = Wo[r * H + k] * LN2;
        } else {
            float s = 0.0f;
            for (int j = 0; j < H; j++) s += Wo[r * H + j];
            v = bo[r] - s;
        }
        sFcO[idx] = make_float2(v, v);
    }
    __syncthreads();

    int q = blockIdx.x * THREADS + threadIdx.x;   // 4 rows per thread
    if (q >= nQuads) return;

    float4 xa = reinterpret_cast<const float4*>(x)[2 * q + 0];  // rows 4q,4q+1
    float4 xb = reinterpret_cast<const float4*>(x)[2 * q + 1];  // rows 4q+2,4q+3
    u64 xa0 = pack2(xa.x, xa.z), xa1 = pack2(xa.y, xa.w);
    u64 xb0 = pack2(xb.x, xb.z), xb1 = pack2(xb.y, xb.w);

    u64 ha[H], hb[H];   // carry G = log2e*(elu(z)+1)

    // ---- fc1 (t-scale) + ELU(G) ----
#pragma unroll
    for (int i = 0; i < H; i++) {
        const ulonglong2* p = reinterpret_cast<const ulonglong2*>(&sFc1[i * 4]);
        ulonglong2 a = p[0];      // {w0d, w1d} x log2e
        ulonglong2 b = p[1];      // {bd, pad}  x log2e
        ha[i] = eluG(fma2(a.x, xa0, fma2(a.y, xa1, b.x)));
        hb[i] = eluG(fma2(a.x, xb0, fma2(a.y, xb1, b.x)));
    }

    // ---- fc2..fc20 : j-major, h[j] consumed once -> no double buffer ----
#pragma unroll 1
    for (int l = 0; l < NMID; l++) {
        const ulonglong2* base =
            reinterpret_cast<const ulonglong2*>(sMid) + l * LSTRIDE_U2;

        u64 acca[H], accb[H];
        {   // bias block (offset 28 u2)
            ulonglong2 b01 = base[28], b23 = base[29], b45 = base[30], b6p = base[31];
            acca[0] = b01.x; accb[0] = b01.x;
            acca[1] = b01.y; accb[1] = b01.y;
            acca[2] = b23.x; accb[2] = b23.x;
            acca[3] = b23.y; accb[3] = b23.y;
            acca[4] = b45.x; accb[4] = b45.x;
            acca[5] = b45.y; accb[5] = b45.y;
            acca[6] = b6p.x; accb[6] = b6p.x;
        }
#pragma unroll
        for (int j = 0; j < H; j++) {
            const ulonglong2* wb = base + j * 4;
            u64 gaj = ha[j], gbj = hb[j];
            ulonglong2 w01 = wb[0];
            acca[0] = fma2(w01.x, gaj, acca[0]);  accb[0] = fma2(w01.x, gbj, accb[0]);
            acca[1] = fma2(w01.y, gaj, acca[1]);  accb[1] = fma2(w01.y, gbj, accb[1]);
            ulonglong2 w23 = wb[1];
            acca[2] = fma2(w23.x, gaj, acca[2]);  accb[2] = fma2(w23.x, gbj, accb[2]);
            acca[3] = fma2(w23.y, gaj, acca[3]);  accb[3] = fma2(w23.y, gbj, accb[3]);
            ulonglong2 w45 = wb[2];
            acca[4] = fma2(w45.x, gaj, acca[4]);  accb[4] = fma2(w45.x, gbj, accb[4]);
            acca[5] = fma2(w45.y, gaj, acca[5]);  accb[5] = fma2(w45.y, gbj, accb[5]);
            ulonglong2 w6p = wb[3];
            acca[6] = fma2(w6p.x, gaj, acca[6]);  accb[6] = fma2(w6p.x, gbj, accb[6]);
        }
#pragma unroll
        for (int i = 0; i < H; i++) {
            ha[i] = eluG(acca[i]);
            hb[i] = eluG(accb[i]);
        }
    }

    // ---- fc21: logits = (ln2*Wo)*G + bias-fold ----
    u64 lpa[2], lpb[2];
#pragma unroll
    for (int r = 0; r < 2; r++) {
        const ulonglong2* p = reinterpret_cast<const ulonglong2*>(&sFcO[r * 8]);
        ulonglong2 q0 = p[0], q1 = p[1], q2 = p[2], q3 = p[3];
        u64 acca = q3.y, accb = q3.y;
        acca = fma2(q0.x, ha[0], acca);  accb = fma2(q0.x, hb[0], accb);
        acca = fma2(q0.y, ha[1], acca);  accb = fma2(q0.y, hb[1], accb);
        acca = fma2(q1.x, ha[2], acca);  accb = fma2(q1.x, hb[2], accb);
        acca = fma2(q1.y, ha[3], acca);  accb = fma2(q1.y, hb[3], accb);
        acca = fma2(q2.x, ha[4], acca);  accb = fma2(q2.x, hb[4], accb);
        acca = fma2(q2.y, ha[5], acca);  accb = fma2(q2.y, hb[5], accb);
        acca = fma2(q3.x, ha[6], acca);  accb = fma2(q3.x, hb[6], accb);
        lpa[r] = acca;  lpb[r] = accb;
    }

    float a0lo, a0hi, a1lo, a1hi, b0lo, b0hi, b1lo, b1hi;
    unpack2(lpa[0], a0lo, a0hi);  unpack2(lpa[1], a1lo, a1hi);
    unpack2(lpb[0], b0lo, b0hi);  unpack2(lpb[1], b1lo, b1hi);

    auto lsm = [](float l0, float l1, float& o0, float& o1) {
        float m   = fmaxf(l0, l1);
        float s   = ex2f((l0 - m) * 1.44269504088896340736f)
                  + ex2f((l1 - m) * 1.44269504088896340736f);
        float lse = m + __logf(s);
        o0 = l0 - lse;  o1 = l1 - lse;
    };

    float4 oa, ob;
    lsm(a0lo, a1lo, oa.x, oa.y);   // row 4q
    lsm(a0hi, a1hi, oa.z, oa.w);   // row 4q+1
    lsm(b0lo, b1lo, ob.x, ob.y);   // row 4q+2
    lsm(b0hi, b1hi, ob.z, ob.w);   // row 4q+3

    reinterpret_cast<float4*>(out)[2 * q + 0] = oa;
    reinterpret_cast<float4*>(out)[2 * q + 1] = ob;
}

extern "C" void kernel_launch(void* const* d_in, const int* in_sizes, int n_in,
                              void* d_out, int out_size)
{
    const float* x  = (const float*)d_in[0];
    const float* W1 = (const float*)d_in[1];
    const float* b1 = (const float*)d_in[2];
    const float* Wm = (const float*)d_in[3];
    const float* bm = (const float*)d_in[4];
    const float* Wo = (const float*)d_in[5];
    const float* bo = (const float*)d_in[6];
    float* out = (float*)d_out;

    int nQuads = in_sizes[0] / 8;   // x is [B,2]; 4 rows per thread
    int grid = (nQuads + THREADS - 1) / THREADS;
    net0_kernel<<<grid, THREADS>>>(x, W1, b1, Wm, bm, Wo, bo, out, nQuads);
}

// round 10
// speedup vs baseline: 1.0801x; 1.0801x over previous
#include <cuda_runtime.h>

// Net0: x[B,2] -> fc1(2,7)+ELU -> 19x fc(7,7)+ELU -> fc(7,2) -> log_softmax.
// R10: 4 rows/thread. Each mid layer is ONE asm block; hidden state crosses
// layers via "+l" constraints (no boundary copies). G-carry algebra (R9):
//   t = z*log2e carried; G = log2e*(elu(z)+1) = log2e*exp2(min(t,0)) + max(t,0)
//   mid weights RAW (ln2*log2e = 1); bias' = (b - rowsum(W))*log2e
//   fc21: logits = (ln2*Wo)*G + (bo - rowsum(Wo))

constexpr int H       = 7;
constexpr int NMID    = 19;
constexpr int THREADS = 256;
// j-major per-layer shared layout (512 B):
//   j*64 + 0 : {W[0][j]d, W[1][j]d}   +16: {W[2][j]d, W[3][j]d}
//   j*64 +32 : {W[4][j]d, W[5][j]d}   +48: {W[6][j]d, pad}
//   448: {b'0d,b'1d} 464:{b'2d,b'3d} 480:{b'4d,b'5d} 496:{b'6d,pad}
constexpr int LSTRIDE_F2 = 64;

typedef unsigned long long u64;

__device__ __forceinline__ u64 pack2(float lo, float hi) {
    u64 r; asm("mov.b64 %0, {%1, %2};" : "=l"(r) : "f"(lo), "f"(hi)); return r;
}
__device__ __forceinline__ void unpack2(u64 v, float& lo, float& hi) {
    asm("mov.b64 {%0, %1}, %2;" : "=f"(lo), "=f"(hi) : "l"(v));
}
__device__ __forceinline__ u64 fma2(u64 a, u64 b, u64 c) {
    u64 d; asm("fma.rn.f32x2 %0, %1, %2, %3;" : "=l"(d) : "l"(a), "l"(b), "l"(c));
    return d;
}
__device__ __forceinline__ float ex2f(float x) {
    float r; asm("ex2.approx.f32 %0, %1;" : "=f"(r) : "f"(x)); return r;
}
// G = log2e*exp2(min(t,0)) + max(t,0)  (scalar, used only in fc1)
__device__ __forceinline__ float eluG1(float t) {
    return fmaf(1.44269504088896340736f, ex2f(fminf(t, 0.0f)), fmaxf(t, 0.0f));
}

// ---- per-layer asm fragments ----
#define JB(o0,o1,o2,o3,HA,HB) \
  "ld.shared.v2.b64 {w0, w1}, [%14+" o0 "];\n\t" \
  "ld.shared.v2.b64 {w2, w3}, [%14+" o1 "];\n\t" \
  "fma.rn.f32x2 vA0, w0, " HA ", vA0;\n\t" \
  "fma.rn.f32x2 vB0, w0, " HB ", vB0;\n\t" \
  "fma.rn.f32x2 vA1, w1, " HA ", vA1;\n\t" \
  "fma.rn.f32x2 vB1, w1, " HB ", vB1;\n\t" \
  "fma.rn.f32x2 vA2, w2, " HA ", vA2;\n\t" \
  "fma.rn.f32x2 vB2, w2, " HB ", vB2;\n\t" \
  "fma.rn.f32x2 vA3, w3, " HA ", vA3;\n\t" \
  "fma.rn.f32x2 vB3, w3, " HB ", vB3;\n\t" \
  "ld.shared.v2.b64 {w0, w1}, [%14+" o2 "];\n\t" \
  "ld.shared.b64 w2, [%14+" o3 "];\n\t" \
  "fma.rn.f32x2 vA4, w0, " HA ", vA4;\n\t" \
  "fma.rn.f32x2 vB4, w0, " HB ", vB4;\n\t" \
  "fma.rn.f32x2 vA5, w1, " HA ", vA5;\n\t" \
  "fma.rn.f32x2 vB5, w1, " HB ", vB5;\n\t" \
  "fma.rn.f32x2 vA6, w2, " HA ", vA6;\n\t" \
  "fma.rn.f32x2 vB6, w2, " HB ", vB6;\n\t"

#define ELU(V, OUT) \
  "mov.b64 {t0, t1}, " V ";\n\t" \
  "min.f32 m0, t0, 0f00000000;\n\t" \
  "min.f32 m1, t1, 0f00000000;\n\t" \
  "ex2.approx.f32 m0, m0;\n\t" \
  "ex2.approx.f32 m1, m1;\n\t" \
  "max.f32 t0, t0, 0f00000000;\n\t" \
  "max.f32 t1, t1, 0f00000000;\n\t" \
  "fma.rn.f32 t0, m0, 0f3FB8AA3B, t0;\n\t" \
  "fma.rn.f32 t1, m1, 0f3FB8AA3B, t1;\n\t" \
  "mov.b64 " OUT ", {t0, t1};\n\t"

__global__ void __launch_bounds__(THREADS, 4)
net0_kernel(const float* __restrict__ x,
            const float* __restrict__ W1, const float* __restrict__ b1,
            const float* __restrict__ Wm, const float* __restrict__ bm,
            const float* __restrict__ Wo, const float* __restrict__ bo,
            float* __restrict__ out, int nQuads)
{
    __shared__ __align__(16) float2 sFc1[H * 4];              // {w0d,w1d,bd,pad} x log2e
    __shared__ __align__(16) float2 sMid[NMID * LSTRIDE_F2];  // j-major, raw W, bias' t-scale
    __shared__ __align__(16) float2 sFcO[2 * 8];              // (ln2*Wo)d + bias-fold d

    const float LOG2E = 1.44269504088896340736f;
    const float LN2   = 0.69314718055994530942f;

    for (int idx = threadIdx.x; idx < H * 4; idx += THREADS) {
        int i = idx >> 2, k = idx & 3;
        float v = (k < 2) ? W1[i * 2 + k] * LOG2E
                          : (k == 2 ? b1[i] * LOG2E : 0.0f);
        sFc1[idx] = make_float2(v, v);
    }
    for (int idx = threadIdx.x; idx < NMID * LSTRIDE_F2; idx += THREADS) {
        int l   = idx >> 6;
        int r   = idx & 63;
        int blk = r >> 3;             // 0..7
        int k   = r & 7;              // 0..7
        float v = 0.0f;
        if (blk < 7) {                // weight block j=blk, neuron i=k (RAW)
            if (k < 7) v = Wm[(l * H + k) * H + blk];
        } else {                      // bias block, t-scale
            if (k < 7) {
                float s = 0.0f;
                for (int j = 0; j < H; j++) s += Wm[(l * H + k) * H + j];
                v = (bm[l * H + k] - s) * LOG2E;
            }
        }
        sMid[idx] = make_float2(v, v);
    }
    for (int idx = threadIdx.x; idx < 16; idx += THREADS) {
        int r = idx >> 3, k = idx & 7;
        float v;
        if (k < 7) {
            v = Wo[r * H + k] * LN2;
        } else {
            float s = 0.0f;
            for (int j = 0; j < H; j++) s += Wo[r * H + j];
            v = bo[r] - s;
        }
        sFcO[idx] = make_float2(v, v);
    }
    __syncthreads();

    int q = blockIdx.x * THREADS + threadIdx.x;   // 4 rows per thread
    if (q >= nQuads) return;

    float4 xa = reinterpret_cast<const float4*>(x)[2 * q + 0];
    float4 xb = reinterpret_cast<const float4*>(x)[2 * q + 1];

    // ---- fc1 (t-scale) + ELU(G), scalar C++ (cold path, once) ----
    float g[4][H];   // [row][i]
#pragma unroll
    for (int i = 0; i < H; i++) {
        float w0 = sFc1[i * 4 + 0].x;
        float w1 = sFc1[i * 4 + 1].x;
        float bb = sFc1[i * 4 + 2].x;
        g[0][i] = eluG1(fmaf(w0, xa.x, fmaf(w1, xa.y, bb)));
        g[1][i] = eluG1(fmaf(w0, xa.z, fmaf(w1, xa.w, bb)));
        g[2][i] = eluG1(fmaf(w0, xb.x, fmaf(w1, xb.y, bb)));
        g[3][i] = eluG1(fmaf(w0, xb.z, fmaf(w1, xb.w, bb)));
    }
    u64 h0a = pack2(g[0][0], g[1][0]), h0b = pack2(g[2][0], g[3][0]);
    u64 h1a = pack2(g[0][1], g[1][1]), h1b = pack2(g[2][1], g[3][1]);
    u64 h2a = pack2(g[0][2], g[1][2]), h2b = pack2(g[2][2], g[3][2]);
    u64 h3a = pack2(g[0][3], g[1][3]), h3b = pack2(g[2][3], g[3][3]);
    u64 h4a = pack2(g[0][4], g[1][4]), h4b = pack2(g[2][4], g[3][4]);
    u64 h5a = pack2(g[0][5], g[1][5]), h5b = pack2(g[2][5], g[3][5]);
    u64 h6a = pack2(g[0][6], g[1][6]), h6b = pack2(g[2][6], g[3][6]);

    unsigned sbase = (unsigned)__cvta_generic_to_shared(sMid);

    // ---- fc2..fc20: one asm block per layer, state in "+l" (no copies) ----
#pragma unroll 1
    for (int l = 0; l < NMID; l++) {
        unsigned saddr = sbase + (unsigned)l * 512u;
        asm volatile(
            "{\n\t"
            ".reg .b64 vA0, vA1, vA2, vA3, vA4, vA5, vA6;\n\t"
            ".reg .b64 vB0, vB1, vB2, vB3, vB4, vB5, vB6;\n\t"
            ".reg .b64 w0, w1, w2, w3;\n\t"
            ".reg .f32 t0, t1, m0, m1;\n\t"
            // bias' (two independent copies via LDS, no MOVs)
            "ld.shared.v2.b64 {vA0, vA1}, [%14+448];\n\t"
            "ld.shared.v2.b64 {vA2, vA3}, [%14+464];\n\t"
            "ld.shared.v2.b64 {vA4, vA5}, [%14+480];\n\t"
            "ld.shared.b64 vA6, [%14+496];\n\t"
            "ld.shared.v2.b64 {vB0, vB1}, [%14+448];\n\t"
            "ld.shared.v2.b64 {vB2, vB3}, [%14+464];\n\t"
            "ld.shared.v2.b64 {vB4, vB5}, [%14+480];\n\t"
            "ld.shared.b64 vB6, [%14+496];\n\t"
            JB(  "0", "16", "32", "48", "%0", "%7")
            JB( "64", "80", "96","112", "%1", "%8")
            JB("128","144","160","176", "%2", "%9")
            JB("192","208","224","240", "%3","%10")
            JB("256","272","288","304", "%4","%11")
            JB("320","336","352","368", "%5","%12")
            JB("384","400","416","432", "%6","%13")
            ELU("vA0", "%0")  ELU("vB0", "%7")
            ELU("vA1", "%1")  ELU("vB1", "%8")
            ELU("vA2", "%2")  ELU("vB2", "%9")
            ELU("vA3", "%3")  ELU("vB3","%10")
            ELU("vA4", "%4")  ELU("vB4","%11")
            ELU("vA5", "%5")  ELU("vB5","%12")
            ELU("vA6", "%6")  ELU("vB6","%13")
            "}"
            : "+l"(h0a), "+l"(h1a), "+l"(h2a), "+l"(h3a),
              "+l"(h4a), "+l"(h5a), "+l"(h6a),
              "+l"(h0b), "+l"(h1b), "+l"(h2b), "+l"(h3b),
              "+l"(h4b), "+l"(h5b), "+l"(h6b)
            : "r"(saddr));
    }

    // ---- fc21: logits = (ln2*Wo)*G + bias-fold ----
    u64 lpa[2], lpb[2];
#pragma unroll
    for (int r = 0; r < 2; r++) {
        const ulonglong2* p = reinterpret_cast<const ulonglong2*>(&sFcO[r * 8]);
        ulonglong2 q0 = p[0], q1 = p[1], q2 = p[2], q3 = p[3];
        u64 acca = q3.y, accb = q3.y;
        acca = fma2(q0.x, h0a, acca);  accb = fma2(q0.x, h0b, accb);
        acca = fma2(q0.y, h1a, acca);  accb = fma2(q0.y, h1b, accb);
        acca = fma2(q1.x, h2a, acca);  accb = fma2(q1.x, h2b, accb);
        acca = fma2(q1.y, h3a, acca);  accb = fma2(q1.y, h3b, accb);
        acca = fma2(q2.x, h4a, acca);  accb = fma2(q2.x, h4b, accb);
        acca = fma2(q2.y, h5a, acca);  accb = fma2(q2.y, h5b, accb);
        acca = fma2(q3.x, h6a, acca);  accb = fma2(q3.x, h6b, accb);
        lpa[r] = acca;  lpb[r] = accb;
    }

    float a0lo, a0hi, a1lo, a1hi, b0lo, b0hi, b1lo, b1hi;
    unpack2(lpa[0], a0lo, a0hi);  unpack2(lpa[1], a1lo, a1hi);
    unpack2(lpb[0], b0lo, b0hi);  unpack2(lpb[1], b1lo, b1hi);

    auto lsm = [](float l0, float l1, float& o0, float& o1) {
        float m   = fmaxf(l0, l1);
        float s   = ex2f((l0 - m) * 1.44269504088896340736f)
                  + ex2f((l1 - m) * 1.44269504088896340736f);
        float lse = m + __logf(s);
        o0 = l0 - lse;  o1 = l1 - lse;
    };

    float4 oa, ob;
    lsm(a0lo, a1lo, oa.x, oa.y);
    lsm(a0hi, a1hi, oa.z, oa.w);
    lsm(b0lo, b1lo, ob.x, ob.y);
    lsm(b0hi, b1hi, ob.z, ob.w);

    reinterpret_cast<float4*>(out)[2 * q + 0] = oa;
    reinterpret_cast<float4*>(out)[2 * q + 1] = ob;
}

extern "C" void kernel_launch(void* const* d_in, const int* in_sizes, int n_in,
                              void* d_out, int out_size)
{
    const float* x  = (const float*)d_in[0];
    const float* W1 = (const float*)d_in[1];
    const float* b1 = (const float*)d_in[2];
    const float* Wm = (const float*)d_in[3];
    const float* bm = (const float*)d_in[4];
    const float* Wo = (const float*)d_in[5];
    const float* bo = (const float*)d_in[6];
    float* out = (float*)d_out;

    int nQuads = in_sizes[0] / 8;   // x is [B,2]; 4 rows per thread
    int grid = (nQuads + THREADS - 1) / THREADS;
    net0_kernel<<<grid, THREADS>>>(x, W1, b1, Wm, bm, Wo, bo, out, nQuads);
}

// round 13
// speedup vs baseline: 1.0999x; 1.0183x over previous
#include <cuda_runtime.h>

// Net0: x[B,2] -> fc1(2,7)+ELU -> 19x fc(7,7)+ELU -> fc(7,2) -> log_softmax.
// R13 = R12 with the fc20 WAR hazard fixed: the final single-layer asm block
// now writes ELU outputs to fresh oA/oB regs and copies to the state operands
// at the END (no state clobber while later steps still read it).
// Design: 4 rows/thread, FFMA2, G-carry t-scale algebra (validated R9/R10),
// i-major steps (MUFU spread), ping-pong double-layer blocks, unique vregs.

constexpr int H       = 7;
constexpr int NMID    = 19;
constexpr int THREADS = 256;

typedef unsigned long long u64;

__device__ __forceinline__ u64 pack2(float lo, float hi) {
    u64 r; asm("mov.b64 %0, {%1, %2};" : "=l"(r) : "f"(lo), "f"(hi)); return r;
}
__device__ __forceinline__ void unpack2(u64 v, float& lo, float& hi) {
    asm("mov.b64 {%0, %1}, %2;" : "=f"(lo), "=f"(hi) : "l"(v));
}
__device__ __forceinline__ u64 fma2(u64 a, u64 b, u64 c) {
    u64 d; asm("fma.rn.f32x2 %0, %1, %2, %3;" : "=l"(d) : "l"(a), "l"(b), "l"(c));
    return d;
}
__device__ __forceinline__ float ex2f(float x) {
    float r; asm("ex2.approx.f32 %0, %1;" : "=f"(r) : "f"(x)); return r;
}
__device__ __forceinline__ float eluG1(float t) {   // scalar, fc1 only
    return fmaf(1.44269504088896340736f, ex2f(fminf(t, 0.0f)), fmaxf(t, 0.0f));
}

// ---- PTX text macros ----
// G = log2e*exp2(min(t,0)) + max(t,0); unique regs per instance.
#define ELUS(ACC,G,E0,E1,M0,M1) \
  "mov.b64 {" E0 "," E1 "}, " ACC ";\n\t" \
  "min.f32 " M0 "," E0 ", 0f00000000;\n\t" \
  "min.f32 " M1 "," E1 ", 0f00000000;\n\t" \
  "ex2.approx.f32 " M0 "," M0 ";\n\t" \
  "ex2.approx.f32 " M1 "," M1 ";\n\t" \
  "max.f32 " E0 "," E0 ", 0f00000000;\n\t" \
  "max.f32 " E1 "," E1 ", 0f00000000;\n\t" \
  "fma.rn.f32 " E0 "," M0 ", 0f3FB8AA3B," E0 ";\n\t" \
  "fma.rn.f32 " E1 "," M1 ", 0f3FB8AA3B," E1 ";\n\t" \
  "mov.b64 " G ", {" E0 "," E1 "};\n\t"

// One i-step: 4x LDS.128 (7 dup weights + dup bias'), 14 fma2 (A/B groups),
// then immediate ELU of both accs (MUFU spread across the layer).
#define STEP_(O0,O1,O2,O3, I0,I1,I2,I3,I4,I5,I6, J0,J1,J2,J3,J4,J5,J6, \
              NA,NB,GA,GB, EA0,EA1,MA0,MA1, EB0,EB1,MB0,MB1) \
  "ld.shared.v2.b64 {w0,w1},[%14+" O0 "];\n\t" \
  "ld.shared.v2.b64 {w2,w3},[%14+" O1 "];\n\t" \
  "ld.shared.v2.b64 {w4,w5},[%14+" O2 "];\n\t" \
  "ld.shared.v2.b64 {w6,w7},[%14+" O3 "];\n\t" \
  "fma.rn.f32x2 " NA ", w0," I0 ", w7;\n\t" \
  "fma.rn.f32x2 " NB ", w0," J0 ", w7;\n\t" \
  "fma.rn.f32x2 " NA ", w1," I1 "," NA ";\n\t" \
  "fma.rn.f32x2 " NB ", w1," J1 "," NB ";\n\t" \
  "fma.rn.f32x2 " NA ", w2," I2 "," NA ";\n\t" \
  "fma.rn.f32x2 " NB ", w2," J2 "," NB ";\n\t" \
  "fma.rn.f32x2 " NA ", w3," I3 "," NA ";\n\t" \
  "fma.rn.f32x2 " NB ", w3," J3 "," NB ";\n\t" \
  "fma.rn.f32x2 " NA ", w4," I4 "," NA ";\n\t" \
  "fma.rn.f32x2 " NB ", w4," J4 "," NB ";\n\t" \
  "fma.rn.f32x2 " NA ", w5," I5 "," NA ";\n\t" \
  "fma.rn.f32x2 " NB ", w5," J5 "," NB ";\n\t" \
  "fma.rn.f32x2 " NA ", w6," I6 "," NA ";\n\t" \
  "fma.rn.f32x2 " NB ", w6," J6 "," NB ";\n\t" \
  ELUS(NA,GA,EA0,EA1,MA0,MA1) \
  ELUS(NB,GB,EB0,EB1,MB0,MB1)

// Variadic trampoline: forces INA/INB to expand BEFORE argument counting.
#define STEP(...) STEP_(__VA_ARGS__)

#define INA "%0","%1","%2","%3","%4","%5","%6"
#define INB "%7","%8","%9","%10","%11","%12","%13"
#define GAS "gA0","gA1","gA2","gA3","gA4","gA5","gA6"
#define GBS "gB0","gB1","gB2","gB3","gB4","gB5","gB6"

__global__ void __launch_bounds__(THREADS, 3)
net0_kernel(const float* __restrict__ x,
            const float* __restrict__ W1, const float* __restrict__ b1,
            const float* __restrict__ Wm, const float* __restrict__ bm,
            const float* __restrict__ Wo, const float* __restrict__ bo,
            float* __restrict__ out, int nQuads)
{
    __shared__ __align__(16) float2 sFc1[H * 4];        // {w0d,w1d,bd,pad} x log2e
    __shared__ __align__(16) float2 sMid[NMID * 64];    // i-major rows: 7w dup + bias' dup
    __shared__ __align__(16) float2 sFcO[2 * 8];        // (ln2*Wo)d + bias-fold d

    const float LOG2E = 1.44269504088896340736f;
    const float LN2   = 0.69314718055994530942f;

    for (int idx = threadIdx.x; idx < H * 4; idx += THREADS) {
        int i = idx >> 2, k = idx & 3;
        float v = (k < 2) ? W1[i * 2 + k] * LOG2E
                          : (k == 2 ? b1[i] * LOG2E : 0.0f);
        sFc1[idx] = make_float2(v, v);
    }
    // per layer: row i (i<7): slots k<7 = RAW Wm[l][i][k], k=7 = (b - rowsum)*log2e.
    for (int idx = threadIdx.x; idx < NMID * 64; idx += THREADS) {
        int l = idx >> 6;
        int r = idx & 63;
        int i = r >> 3, k = r & 7;
        float v = 0.0f;
        if (i < 7) {
            if (k < 7) {
                v = Wm[(l * H + i) * H + k];
            } else {
                float s = 0.0f;
                for (int j = 0; j < H; j++) s += Wm[(l * H + i) * H + j];
                v = (bm[l * H + i] - s) * LOG2E;
            }
        }
        sMid[idx] = make_float2(v, v);
    }
    for (int idx = threadIdx.x; idx < 16; idx += THREADS) {
        int r = idx >> 3, k = idx & 7;
        float v;
        if (k < 7) {
            v = Wo[r * H + k] * LN2;
        } else {
            float s = 0.0f;
            for (int j = 0; j < H; j++) s += Wo[r * H + j];
            v = bo[r] - s;
        }
        sFcO[idx] = make_float2(v, v);
    }
    __syncthreads();

    int q = blockIdx.x * THREADS + threadIdx.x;   // 4 rows per thread
    if (q >= nQuads) return;

    float4 xa = reinterpret_cast<const float4*>(x)[2 * q + 0];
    float4 xb = reinterpret_cast<const float4*>(x)[2 * q + 1];

    // ---- fc1 (t-scale) + ELU(G), scalar ----
    float g[4][H];
#pragma unroll
    for (int i = 0; i < H; i++) {
        float w0 = sFc1[i * 4 + 0].x;
        float w1 = sFc1[i * 4 + 1].x;
        float bb = sFc1[i * 4 + 2].x;
        g[0][i] = eluG1(fmaf(w0, xa.x, fmaf(w1, xa.y, bb)));
        g[1][i] = eluG1(fmaf(w0, xa.z, fmaf(w1, xa.w, bb)));
        g[2][i] = eluG1(fmaf(w0, xb.x, fmaf(w1, xb.y, bb)));
        g[3][i] = eluG1(fmaf(w0, xb.z, fmaf(w1, xb.w, bb)));
    }
    u64 h0a = pack2(g[0][0], g[1][0]), h0b = pack2(g[2][0], g[3][0]);
    u64 h1a = pack2(g[0][1], g[1][1]), h1b = pack2(g[2][1], g[3][1]);
    u64 h2a = pack2(g[0][2], g[1][2]), h2b = pack2(g[2][2], g[3][2]);
    u64 h3a = pack2(g[0][3], g[1][3]), h3b = pack2(g[2][3], g[3][3]);
    u64 h4a = pack2(g[0][4], g[1][4]), h4b = pack2(g[2][4], g[3][4]);
    u64 h5a = pack2(g[0][5], g[1][5]), h5b = pack2(g[2][5], g[3][5]);
    u64 h6a = pack2(g[0][6], g[1][6]), h6b = pack2(g[2][6], g[3][6]);

    unsigned sbase = (unsigned)__cvta_generic_to_shared(sMid);

    // ---- fc2..fc19: 9 ping-pong double-layer blocks ----
#pragma unroll 1
    for (int l = 0; l < 9; l++) {
        unsigned saddr = sbase + (unsigned)l * 1024u;
        asm volatile(
            "{\n\t"
            ".reg .b64 w<8>, nA<7>, nB<7>, pA<7>, pB<7>, gA<7>, gB<7>;\n\t"
            ".reg .f32 ea<14>, ma<14>, eb<14>, mb<14>;\n\t"
            ".reg .f32 ua<14>, va<14>, ub<14>, vb<14>;\n\t"
            // ---- layer A: state -> gA/gB (reads %0..%13, writes gA/gB) ----
            STEP(  "0", "16", "32", "48", INA, INB, "nA0","nB0","gA0","gB0",
                 "ea0","ea1","ma0","ma1","eb0","eb1","mb0","mb1")
            STEP( "64", "80", "96","112", INA, INB, "nA1","nB1","gA1","gB1",
                 "ea2","ea3","ma2","ma3","eb2","eb3","mb2","mb3")
            STEP("128","144","160","176", INA, INB, "nA2","nB2","gA2","gB2",
                 "ea4","ea5","ma4","ma5","eb4","eb5","mb4","mb5")
            STEP("192","208","224","240", INA, INB, "nA3","nB3","gA3","gB3",
                 "ea6","ea7","ma6","ma7","eb6","eb7","mb6","mb7")
            STEP("256","272","288","304", INA, INB, "nA4","nB4","gA4","gB4",
                 "ea8","ea9","ma8","ma9","eb8","eb9","mb8","mb9")
            STEP("320","336","352","368", INA, INB, "nA5","nB5","gA5","gB5",
                 "ea10","ea11","ma10","ma11","eb10","eb11","mb10","mb11")
            STEP("384","400","416","432", INA, INB, "nA6","nB6","gA6","gB6",
                 "ea12","ea13","ma12","ma13","eb12","eb13","mb12","mb13")
            // ---- layer B: gA/gB -> state (reads gA/gB, writes %0..%13) ----
            STEP("512","528","544","560", GAS, GBS, "pA0","pB0","%0","%7",
                 "ua0","ua1","va0","va1","ub0","ub1","vb0","vb1")
            STEP("576","592","608","624", GAS, GBS, "pA1","pB1","%1","%8",
                 "ua2","ua3","va2","va3","ub2","ub3","vb2","vb3")
            STEP("640","656","672","688", GAS, GBS, "pA2","pB2","%2","%9",
                 "ua4","ua5","va4","va5","ub4","ub5","vb4","vb5")
            STEP("704","720","736","752", GAS, GBS, "pA3","pB3","%3","%10",
                 "ua6","ua7","va6","va7","ub6","ub7","vb6","vb7")
            STEP("768","784","800","816", GAS, GBS, "pA4","pB4","%4","%11",
                 "ua8","ua9","va8","va9","ub8","ub9","vb8","vb9")
            STEP("832","848","864","880", GAS, GBS, "pA5","pB5","%5","%12",
                 "ua10","ua11","va10","va11","ub10","ub11","vb10","vb11")
            STEP("896","912","928","944", GAS, GBS, "pA6","pB6","%6","%13",
                 "ua12","ua13","va12","va13","ub12","ub13","vb12","vb13")
            "}"
            : "+l"(h0a), "+l"(h1a), "+l"(h2a), "+l"(h3a),
              "+l"(h4a), "+l"(h5a), "+l"(h6a),
              "+l"(h0b), "+l"(h1b), "+l"(h2b), "+l"(h3b),
              "+l"(h4b), "+l"(h5b), "+l"(h6b)
            : "r"(saddr));
    }

    // ---- fc20 (layer 19): single block. WAR-safe: ELU outputs go to fresh
    //      oA/oB regs; state is updated by movs at the END of the block. ----
    {
        unsigned saddr = sbase + 9216u;   // 18 * 512
        asm volatile(
            "{\n\t"
            ".reg .b64 w<8>, nA<7>, nB<7>, oA<7>, oB<7>;\n\t"
            ".reg .f32 ea<14>, ma<14>, eb<14>, mb<14>;\n\t"
            STEP(  "0", "16", "32", "48", INA, INB, "nA0","nB0","oA0","oB0",
                 "ea0","ea1","ma0","ma1","eb0","eb1","mb0","mb1")
            STEP( "64", "80", "96","112", INA, INB, "nA1","nB1","oA1","oB1",
                 "ea2","ea3","ma2","ma3","eb2","eb3","mb2","mb3")
            STEP("128","144","160","176", INA, INB, "nA2","nB2","oA2","oB2",
                 "ea4","ea5","ma4","ma5","eb4","eb5","mb4","mb5")
            STEP("192","208","224","240", INA, INB, "nA3","nB3","oA3","oB3",
                 "ea6","ea7","ma6","ma7","eb6","eb7","mb6","mb7")
            STEP("256","272","288","304", INA, INB, "nA4","nB4","oA4","oB4",
                 "ea8","ea9","ma8","ma9","eb8","eb9","mb8","mb9")
            STEP("320","336","352","368", INA, INB, "nA5","nB5","oA5","oB5",
                 "ea10","ea11","ma10","ma11","eb10","eb11","mb10","mb11")
            STEP("384","400","416","432", INA, INB, "nA6","nB6","oA6","oB6",
                 "ea12","ea13","ma12","ma13","eb12","eb13","mb12","mb13")
            "mov.b64 %0, oA0;\n\t"  "mov.b64 %7,  oB0;\n\t"
            "mov.b64 %1, oA1;\n\t"  "mov.b64 %8,  oB1;\n\t"
            "mov.b64 %2, oA2;\n\t"  "mov.b64 %9,  oB2;\n\t"
            "mov.b64 %3, oA3;\n\t"  "mov.b64 %10, oB3;\n\t"
            "mov.b64 %4, oA4;\n\t"  "mov.b64 %11, oB4;\n\t"
            "mov.b64 %5, oA5;\n\t"  "mov.b64 %12, oB5;\n\t"
            "mov.b64 %6, oA6;\n\t"  "mov.b64 %13, oB6;\n\t"
            "}"
            : "+l"(h0a), "+l"(h1a), "+l"(h2a), "+l"(h3a),
              "+l"(h4a), "+l"(h5a), "+l"(h6a),
              "+l"(h0b), "+l"(h1b), "+l"(h2b), "+l"(h3b),
              "+l"(h4b), "+l"(h5b), "+l"(h6b)
            : "r"(saddr));
    }

    // ---- fc21: logits = (ln2*Wo)*G + bias-fold ----
    u64 lpa[2], lpb[2];
#pragma unroll
    for (int r = 0; r < 2; r++) {
        const ulonglong2* p = reinterpret_cast<const ulonglong2*>(&sFcO[r * 8]);
        ulonglong2 q0 = p[0], q1 = p[1], q2 = p[2], q3 = p[3];
        u64 acca = q3.y, accb = q3.y;
        acca = fma2(q0.x, h0a, acca);  accb = fma2(q0.x, h0b, accb);
        acca = fma2(q0.y, h1a, acca);  accb = fma2(q0.y, h1b, accb);
        acca = fma2(q1.x, h2a, acca);  accb = fma2(q1.x, h2b, accb);
        acca = fma2(q1.y, h3a, acca);  accb = fma2(q1.y, h3b, accb);
        acca = fma2(q2.x, h4a, acca);  accb = fma2(q2.x, h4b, accb);
        acca = fma2(q2.y, h5a, acca);  accb = fma2(q2.y, h5b, accb);
        acca = fma2(q3.x, h6a, acca);  accb = fma2(q3.x, h6b, accb);
        lpa[r] = acca;  lpb[r] = accb;
    }

    float a0lo, a0hi, a1lo, a1hi, b0lo, b0hi, b1lo, b1hi;
    unpack2(lpa[0], a0lo, a0hi);  unpack2(lpa[1], a1lo, a1hi);
    unpack2(lpb[0], b0lo, b0hi);  unpack2(lpb[1], b1lo, b1hi);

    auto lsm = [](float l0, float l1, float& o0, float& o1) {
        float m   = fmaxf(l0, l1);
        float s   = ex2f((l0 - m) * 1.44269504088896340736f)
                  + ex2f((l1 - m) * 1.44269504088896340736f);
        float lse = m + __logf(s);
        o0 = l0 - lse;  o1 = l1 - lse;
    };

    float4 oa, ob;
    lsm(a0lo, a1lo, oa.x, oa.y);
    lsm(a0hi, a1hi, oa.z, oa.w);
    lsm(b0lo, b1lo, ob.x, ob.y);
    lsm(b0hi, b1hi, ob.z, ob.w);

    reinterpret_cast<float4*>(out)[2 * q + 0] = oa;
    reinterpret_cast<float4*>(out)[2 * q + 1] = ob;
}

extern "C" void kernel_launch(void* const* d_in, const int* in_sizes, int n_in,
                              void* d_out, int out_size)
{
    const float* x  = (const float*)d_in[0];
    const float* W1 = (const float*)d_in[1];
    const float* b1 = (const float*)d_in[2];
    const float* Wm = (const float*)d_in[3];
    const float* bm = (const float*)d_in[4];
    const float* Wo = (const float*)d_in[5];
    const float* bo = (const float*)d_in[6];
    float* out = (float*)d_out;

    int nQuads = in_sizes[0] / 8;   // x is [B,2]; 4 rows per thread
    int grid = (nQuads + THREADS - 1) / THREADS;
    net0_kernel<<<grid, THREADS>>>(x, W1, b1, Wm, bm, Wo, bo, out, nQuads);
}